// round 16
// baseline (speedup 1.0000x reference)
#include <cuda_runtime.h>
#include <cuda_fp16.h>
#include <cuda_pipeline.h>
#include <mma.h>
#include <cstdint>

using namespace nvcuda;

#define N_CELLS 8192
#define D_GENE  1024
#define D_EMB   256
#define KCAT    768   // [hi | lo | hi] split concat along K

// ---------------- scratch (device globals; no allocation allowed) ----------------
__device__ __half g_Bcat[(size_t)N_CELLS * KCAT];   // [Eh | Eh | El]   [N,K]
__device__ __half g_Acat[(size_t)N_CELLS * KCAT];   // [Ph | Pl | Ph]   [M,K]
__device__ __half g_B2[(size_t)KCAT * D_EMB];       // [Th ; Tl ; Th]   [K,N]
__device__ __half g_Xh[(size_t)N_CELLS * D_GENE];   // expression fp16  [K,N]
__device__ __half g_Gh[(size_t)D_GENE * D_GENE];    // gene_response    [K,N]
__device__ __half g_gated[(size_t)N_CELLS * N_CELLS]; // gated matrix   128 MB
__device__ __half g_M1h[(size_t)N_CELLS * D_GENE];  // (gated@expr)

// ---------------- conversion kernels (R1 originals, proven) ----------------
__global__ void k_cvt_expr(const float* __restrict__ in) {
    int i = blockIdx.x * blockDim.x + threadIdx.x;
    if (i < N_CELLS * D_GENE) g_Xh[i] = __float2half_rn(in[i]);
}

__global__ void k_cvt_gr(const float* __restrict__ in) {
    int i = blockIdx.x * blockDim.x + threadIdx.x;
    if (i < D_GENE * D_GENE) g_Gh[i] = __float2half_rn(in[i]);
}

__global__ void k_cvt_enc(const float* __restrict__ enc) {
    int i = blockIdx.x * blockDim.x + threadIdx.x;
    if (i >= N_CELLS * D_EMB) return;
    int m = i / D_EMB, c = i % D_EMB;
    float x = enc[i];
    __half h = __float2half_rn(x);
    __half l = __float2half_rn(x - __half2float(h));
    size_t base = (size_t)m * KCAT + c;
    g_Bcat[base]             = h;
    g_Bcat[base + D_EMB]     = h;
    g_Bcat[base + 2 * D_EMB] = l;
}

__global__ void k_cvt_T(const float* __restrict__ T) {
    int i = blockIdx.x * blockDim.x + threadIdx.x;
    if (i >= D_EMB * D_EMB) return;
    int k = i / D_EMB, j = i % D_EMB;
    float x = T[i];
    __half h = __float2half_rn(x);
    __half l = __float2half_rn(x - __half2float(h));
    g_B2[(size_t)k * D_EMB + j]               = h;
    g_B2[(size_t)(k + D_EMB) * D_EMB + j]     = l;
    g_B2[(size_t)(k + 2 * D_EMB) * D_EMB + j] = h;
}

// gate math: spatial = exp(-pd/1e4) = 1 - pd*1e-4 (Taylor, err<5e-9 for pd in [0,1]);
// sigmoid saturates for |v|>10 (err<4.5e-5 < fp16 ulp of gated) -> MUFU on ~3% only.
__device__ __forceinline__ float gate_fn(float pd, float v) {
    float sp = fmaf(pd, -1e-4f, 1.0f);
    float sig;
    if (fabsf(v) < 10.0f)
        sig = __fdividef(1.0f, 1.0f + __expf(-v));
    else
        sig = (v > 0.0f) ? 1.0f : 0.0f;
    return sp * sig;
}

// ---------------- wmma GEMM: CTA 128x128 (4 warps, 64x64 each), k-chunk 64 -------
// Half the sync frequency of R12/R15. 2 stages x 40960 B dyn smem -> 2 CTAs/SM.
// Stage = two k32 sub-chunks, each with the R15-proven pitch-40/136 layout.
//   iter it: wait_prior(0) -> sync -> issue copy(it+1 -> buf^1) -> compute(it)
// MODE 0: P   = Bcat @ B2        (M=8192, N=256,  K=768)   B row-major [K,N]
// MODE 1: S   = Acat @ Bcat^T    (M=8192, N=8192, K=768)   B col-major [N,K]
// MODE 2: M1  = gated @ Xh       (M=8192, N=1024, K=8192)  B row-major [K,N]
// MODE 3: out = M1h @ Gh         (M=8192, N=1024, K=1024)  B row-major [K,N]
#define SUB_B   10240                 // one k32 sub-chunk (A or B region)
#define STAGE_B 40960                 // A: 2 subs (20480) + B: 2 subs (20480)
#define DSMEM_B (2 * STAGE_B)         // 81920

template <int MODE>
__global__ __launch_bounds__(128, 2)
void gemm_wmma11(const float* __restrict__ aux, float* __restrict__ outf) {
    constexpr bool B_COL = (MODE == 1);
    constexpr int K    = (MODE <= 1) ? KCAT : (MODE == 2 ? N_CELLS : D_GENE);
    constexpr int NK   = K / 64;
    constexpr int Ndim = (MODE == 0) ? D_EMB : (MODE == 1 ? N_CELLS : D_GENE);
    constexpr int LDA  = 40;                  // pitch (halves): 32 data + 8 pad

    const __half* __restrict__ A =
        (MODE == 0) ? g_Bcat : (MODE == 1) ? g_Acat : (MODE == 2) ? g_gated : g_M1h;
    const __half* __restrict__ B =
        (MODE == 0) ? g_B2 : (MODE == 1) ? g_Bcat : (MODE == 2) ? g_Xh : g_Gh;

    extern __shared__ __align__(16) char dsm[];
    // stage buf in {0,1}; sub c in {0,1}
    auto AsP = [&](int buf, int c) { return (__half*)(dsm + buf * STAGE_B + c * SUB_B); };
    auto BsP = [&](int buf, int c) { return (__half*)(dsm + buf * STAGE_B + 20480 + c * SUB_B); };

    const int tid  = threadIdx.x;    // 0..127
    const int lane = tid & 31;
    const int w    = tid >> 5;       // 0..3
    const int wm   = w >> 1;         // 0..1 -> m offset wm*64
    const int wn   = w & 1;          // 0..1 -> n offset wn*64
    const size_t gm0 = (size_t)blockIdx.y * 128;
    const size_t gn0 = (size_t)blockIdx.x * 128;

    wmma::fragment<wmma::accumulator, 16, 16, 16, float> acc[4][4];
#pragma unroll
    for (int i = 0; i < 4; i++)
#pragma unroll
        for (int j = 0; j < 4; j++) wmma::fill_fragment(acc[i][j], 0.0f);

    // ---- async stage copy: k64 = two k32 sub-chunk copies (R15-proven body) ----
    auto load_stage = [&](int it, int buf) {
        const int kbase = it * 64;
#pragma unroll
        for (int c = 0; c < 2; c++) {
            const int k0 = kbase + c * 32;
            __half* sA = AsP(buf, c);
            __half* sB = BsP(buf, c);
#pragma unroll
            for (int j = 0; j < 4; j++) {
                int idx = tid + j * 128;
                int row = idx >> 2, ch = idx & 3;    // A: 128 rows x 4 chunks(16B)
                __pipeline_memcpy_async(&sA[row * LDA + ch * 8],
                                        A + (gm0 + row) * (size_t)K + k0 + ch * 8, 16);
            }
            if (B_COL) {
#pragma unroll
                for (int j = 0; j < 4; j++) {
                    int idx = tid + j * 128;
                    int row = idx >> 2, ch = idx & 3;
                    __pipeline_memcpy_async(&sB[row * 40 + ch * 8],
                                            B + (gn0 + row) * (size_t)K + k0 + ch * 8, 16);
                }
            } else {
#pragma unroll
                for (int j = 0; j < 4; j++) {
                    int idx = tid + j * 128;
                    int row = idx >> 4, ch = idx & 15;   // 32 rows x 16 chunks
                    __pipeline_memcpy_async(&sB[row * 136 + ch * 8],
                                            B + (size_t)(k0 + row) * Ndim + gn0 + ch * 8, 16);
                }
            }
        }
        __pipeline_commit();
    };

    load_stage(0, 0);

#pragma unroll 1
    for (int it = 0; it < NK; ++it) {
        const int buf = it & 1;
        __pipeline_wait_prior(0);   // stage `it` complete
        __syncthreads();            // visible; reads of buf^1 (iter it-1) done
        if (it + 1 < NK) load_stage(it + 1, buf ^ 1);   // lands under a k64 compute phase

#pragma unroll
        for (int c = 0; c < 2; c++) {
            const __half* sA = AsP(buf, c);
            const __half* sB = BsP(buf, c);
#pragma unroll
            for (int kk = 0; kk < 32; kk += 16) {
                if constexpr (B_COL) {
                    wmma::fragment<wmma::matrix_b, 16, 16, 16, __half, wmma::col_major> b[4];
#pragma unroll
                    for (int nt = 0; nt < 4; nt++)
                        wmma::load_matrix_sync(b[nt], &sB[(wn * 64 + nt * 16) * 40 + kk], 40);
#pragma unroll
                    for (int mt = 0; mt < 4; mt++) {
                        wmma::fragment<wmma::matrix_a, 16, 16, 16, __half, wmma::row_major> a;
                        wmma::load_matrix_sync(a, &sA[(wm * 64 + mt * 16) * LDA + kk], LDA);
#pragma unroll
                        for (int nt = 0; nt < 4; nt++)
                            wmma::mma_sync(acc[mt][nt], a, b[nt], acc[mt][nt]);
                    }
                } else {
                    wmma::fragment<wmma::matrix_b, 16, 16, 16, __half, wmma::row_major> b[4];
#pragma unroll
                    for (int nt = 0; nt < 4; nt++)
                        wmma::load_matrix_sync(b[nt], &sB[kk * 136 + wn * 64 + nt * 16], 136);
#pragma unroll
                    for (int mt = 0; mt < 4; mt++) {
                        wmma::fragment<wmma::matrix_a, 16, 16, 16, __half, wmma::row_major> a;
                        wmma::load_matrix_sync(a, &sA[(wm * 64 + mt * 16) * LDA + kk], LDA);
#pragma unroll
                        for (int nt = 0; nt < 4; nt++)
                            wmma::mma_sync(acc[mt][nt], a, b[nt], acc[mt][nt]);
                    }
                }
            }
        }
    }

    // ---------------- epilogue (per-warp staging; aliases stage 0) ----------------
    __syncthreads();   // all compute done before overwriting stage smem
    float* epbuf = (float*)dsm + w * 320;   // 4 warps x 16x20 floats = 5120 B

    const int r  = lane >> 1;
    const int cb = (lane & 1) * 8;
#pragma unroll
    for (int mt = 0; mt < 4; mt++) {
        const size_t gr = gm0 + wm * 64 + mt * 16 + r;
#pragma unroll
        for (int nt = 0; nt < 4; nt++) {
            wmma::store_matrix_sync(epbuf, acc[mt][nt], 20, wmma::mem_row_major);
            __syncwarp();
            const size_t gc = gn0 + wn * 64 + nt * 16 + cb;
            float v[8];
#pragma unroll
            for (int e = 0; e < 8; e++) v[e] = epbuf[r * 20 + cb + e];

            if constexpr (MODE == 0) {
                __half2 hh[4], ll[4];
#pragma unroll
                for (int e = 0; e < 4; e++) {
                    __half h0 = __float2half_rn(v[e * 2]);
                    __half h1 = __float2half_rn(v[e * 2 + 1]);
                    hh[e] = __halves2half2(h0, h1);
                    ll[e] = __halves2half2(
                        __float2half_rn(v[e * 2]     - __half2float(h0)),
                        __float2half_rn(v[e * 2 + 1] - __half2float(h1)));
                }
                size_t base = gr * KCAT + gc;
                *(uint4*)(g_Acat + base)             = *(uint4*)hh;
                *(uint4*)(g_Acat + base + D_EMB)     = *(uint4*)ll;
                *(uint4*)(g_Acat + base + 2 * D_EMB) = *(uint4*)hh;
            } else if constexpr (MODE == 1) {
                const float* prow = aux + gr * (size_t)N_CELLS + gc;
                float4 p0 = __ldcs((const float4*)prow);
                float4 p1 = __ldcs((const float4*)(prow + 4));
                float pv[8] = {p0.x, p0.y, p0.z, p0.w, p1.x, p1.y, p1.z, p1.w};
                __half2 o[4];
#pragma unroll
                for (int e = 0; e < 4; e++) {
                    float s0 = gate_fn(pv[e * 2],     v[e * 2]);
                    float s1 = gate_fn(pv[e * 2 + 1], v[e * 2 + 1]);
                    o[e] = __floats2half2_rn(s0, s1);
                }
                *(uint4*)(g_gated + gr * (size_t)N_CELLS + gc) = *(uint4*)o;
            } else if constexpr (MODE == 2) {
                __half2 o[4];
#pragma unroll
                for (int e = 0; e < 4; e++)
                    o[e] = __floats2half2_rn(v[e * 2], v[e * 2 + 1]);
                *(uint4*)(g_M1h + gr * D_GENE + gc) = *(uint4*)o;
            } else {
                float4 o0 = make_float4(v[0] * (1.0f / 1024.0f), v[1] * (1.0f / 1024.0f),
                                        v[2] * (1.0f / 1024.0f), v[3] * (1.0f / 1024.0f));
                float4 o1 = make_float4(v[4] * (1.0f / 1024.0f), v[5] * (1.0f / 1024.0f),
                                        v[6] * (1.0f / 1024.0f), v[7] * (1.0f / 1024.0f));
                *(float4*)(outf + gr * D_GENE + gc)     = o0;
                *(float4*)(outf + gr * D_GENE + gc + 4) = o1;
            }
            __syncwarp();
        }
    }
}

// ---------------- launch ----------------
extern "C" void kernel_launch(void* const* d_in, const int* in_sizes, int n_in,
                              void* d_out, int out_size) {
    const float* expr = (const float*)d_in[0];
    const float* enc  = (const float*)d_in[1];
    const float* pd   = (const float*)d_in[2];
    const float* T    = (const float*)d_in[3];
    const float* gr   = (const float*)d_in[4];
    float* out = (float*)d_out;

    cudaFuncSetAttribute(gemm_wmma11<0>, cudaFuncAttributeMaxDynamicSharedMemorySize, DSMEM_B);
    cudaFuncSetAttribute(gemm_wmma11<1>, cudaFuncAttributeMaxDynamicSharedMemorySize, DSMEM_B);
    cudaFuncSetAttribute(gemm_wmma11<2>, cudaFuncAttributeMaxDynamicSharedMemorySize, DSMEM_B);
    cudaFuncSetAttribute(gemm_wmma11<3>, cudaFuncAttributeMaxDynamicSharedMemorySize, DSMEM_B);

    // Order chosen so the 4th launch (ncu capture slot) is the dominant GEMM1.
    k_cvt_enc<<<(N_CELLS * D_EMB) / 256, 256>>>(enc);
    k_cvt_T<<<(D_EMB * D_EMB) / 256, 256>>>(T);
    gemm_wmma11<0><<<dim3(D_EMB / 128,  N_CELLS / 128), 128, DSMEM_B>>>(nullptr, nullptr);
    gemm_wmma11<1><<<dim3(N_CELLS / 128, N_CELLS / 128), 128, DSMEM_B>>>(pd, nullptr);
    k_cvt_expr<<<(N_CELLS * D_GENE) / 256, 256>>>(expr);
    k_cvt_gr<<<(D_GENE * D_GENE) / 256, 256>>>(gr);
    gemm_wmma11<2><<<dim3(D_GENE / 128, N_CELLS / 128), 128, DSMEM_B>>>(nullptr, nullptr);
    gemm_wmma11<3><<<dim3(D_GENE / 128, N_CELLS / 128), 128, DSMEM_B>>>(nullptr, out);
}

// round 17
// speedup vs baseline: 1.1600x; 1.1600x over previous
#include <cuda_runtime.h>
#include <cuda_fp16.h>
#include <cuda_pipeline.h>
#include <mma.h>
#include <cstdint>

using namespace nvcuda;

#define N_CELLS 8192
#define D_GENE  1024
#define D_EMB   256
#define KCAT    768   // [hi | lo | hi] split concat along K

// ---------------- scratch (device globals; no allocation allowed) ----------------
__device__ __half g_Bcat[(size_t)N_CELLS * KCAT];   // [Eh | Eh | El]   [N,K]
__device__ __half g_Acat[(size_t)N_CELLS * KCAT];   // [Ph | Pl | Ph]   [M,K]
__device__ __half g_B2[(size_t)KCAT * D_EMB];       // [Th ; Tl ; Th]   [K,N]
__device__ __half g_Xh[(size_t)N_CELLS * D_GENE];   // expression fp16  [K,N]
__device__ __half g_Gh[(size_t)D_GENE * D_GENE];    // gene_response    [K,N]
__device__ __half g_gated[(size_t)N_CELLS * N_CELLS]; // gated matrix   128 MB
__device__ __half g_M1a[(size_t)N_CELLS * D_GENE];  // (gated@expr) K-half 0
__device__ __half g_M1b[(size_t)N_CELLS * D_GENE];  // (gated@expr) K-half 1

// ---------------- conversion kernels (R1 originals, proven) ----------------
__global__ void k_cvt_expr(const float* __restrict__ in) {
    int i = blockIdx.x * blockDim.x + threadIdx.x;
    if (i < N_CELLS * D_GENE) g_Xh[i] = __float2half_rn(in[i]);
}

__global__ void k_cvt_gr(const float* __restrict__ in) {
    int i = blockIdx.x * blockDim.x + threadIdx.x;
    if (i < D_GENE * D_GENE) g_Gh[i] = __float2half_rn(in[i]);
}

__global__ void k_cvt_enc(const float* __restrict__ enc) {
    int i = blockIdx.x * blockDim.x + threadIdx.x;
    if (i >= N_CELLS * D_EMB) return;
    int m = i / D_EMB, c = i % D_EMB;
    float x = enc[i];
    __half h = __float2half_rn(x);
    __half l = __float2half_rn(x - __half2float(h));
    size_t base = (size_t)m * KCAT + c;
    g_Bcat[base]             = h;
    g_Bcat[base + D_EMB]     = h;
    g_Bcat[base + 2 * D_EMB] = l;
}

__global__ void k_cvt_T(const float* __restrict__ T) {
    int i = blockIdx.x * blockDim.x + threadIdx.x;
    if (i >= D_EMB * D_EMB) return;
    int k = i / D_EMB, j = i % D_EMB;
    float x = T[i];
    __half h = __float2half_rn(x);
    __half l = __float2half_rn(x - __half2float(h));
    g_B2[(size_t)k * D_EMB + j]               = h;
    g_B2[(size_t)(k + D_EMB) * D_EMB + j]     = l;
    g_B2[(size_t)(k + 2 * D_EMB) * D_EMB + j] = h;
}

// gate math: spatial = exp(-pd/1e4) = 1 - pd*1e-4 (Taylor, err<5e-9 for pd in [0,1]);
// sigmoid saturates for |v|>10 (err<4.5e-5 < fp16 ulp of gated) -> MUFU on ~3% only.
__device__ __forceinline__ float gate_fn(float pd, float v) {
    float sp = fmaf(pd, -1e-4f, 1.0f);
    float sig;
    if (fabsf(v) < 10.0f)
        sig = __fdividef(1.0f, 1.0f + __expf(-v));
    else
        sig = (v > 0.0f) ? 1.0f : 0.0f;
    return sp * sig;
}

// ---------------- wmma GEMM: CTA 128x128 (4 warps, 64x64 each), k-chunk 32 -------
// R15-proven 3-stage cp.async pipeline (wait_prior(1), tail (0)), 12 warps/SM.
// MODE 0: P    = Bcat @ B2       (M=8192, N=256,  K=768)   B row-major [K,N]
// MODE 1: S    = Acat @ Bcat^T   (M=8192, N=8192, K=768)   B col-major [N,K]
// MODE 2: M1ab = gated @ Xh      split-K=2 via blockIdx.z  B row-major [K,N]
// MODE 3: out  = (M1a+M1b) @ Gh  (K=1024) A = fp16 sum via reg-prefetch LDG+HADD2
#define STAGE_B 20480
#define DSMEM_B (3 * STAGE_B)   // 61440

template <int MODE>
__global__ __launch_bounds__(128, (MODE == 3) ? 2 : 3)
void gemm_wmma12(const float* __restrict__ aux, float* __restrict__ outf) {
    constexpr bool B_COL  = (MODE == 1);
    constexpr bool DUAL_A = (MODE == 3);
    constexpr int K    = (MODE <= 1) ? KCAT : (MODE == 2 ? N_CELLS : D_GENE);  // row stride
    constexpr int KLOC = (MODE == 2) ? (N_CELLS / 2) : K;   // per-CTA K extent
    constexpr int NK   = KLOC / 32;
    constexpr int Ndim = (MODE == 0) ? D_EMB : (MODE == 1 ? N_CELLS : D_GENE);
    constexpr int LDA  = 40;                  // pitch (halves): 32 data + 8 pad

    const __half* __restrict__ A =
        (MODE == 0) ? g_Bcat : (MODE == 1) ? g_Acat : g_gated;   // unused for MODE 3
    const __half* __restrict__ B =
        (MODE == 0) ? g_B2 : (MODE == 1) ? g_Bcat : (MODE == 2) ? g_Xh : g_Gh;

    extern __shared__ __align__(16) char dsm[];
    auto AsP = [&](int buf) { return (__half*)(dsm + buf * STAGE_B); };
    auto BsP = [&](int buf) { return (__half*)(dsm + buf * STAGE_B + 10240); };

    const int tid  = threadIdx.x;    // 0..127
    const int lane = tid & 31;
    const int w    = tid >> 5;       // 0..3
    const int wm   = w >> 1;         // 0..1 -> m offset wm*64
    const int wn   = w & 1;          // 0..1 -> n offset wn*64
    const size_t gm0 = (size_t)blockIdx.y * 128;
    const size_t gn0 = (size_t)blockIdx.x * 128;
    const int kbase  = (MODE == 2) ? blockIdx.z * (N_CELLS / 2) : 0;

    wmma::fragment<wmma::accumulator, 16, 16, 16, float> acc[4][4];
#pragma unroll
    for (int i = 0; i < 4; i++)
#pragma unroll
        for (int j = 0; j < 4; j++) wmma::fill_fragment(acc[i][j], 0.0f);

    // ---- MODE 3: A = M1a + M1b via register prefetch (R10-proven schedule) ----
    uint4 rA[4];
    auto fetchA = [&](int it) {
        if constexpr (DUAL_A) {
            const int k0 = it * 32;
#pragma unroll
            for (int j = 0; j < 4; j++) {
                int idx = tid + j * 128;
                int row = idx >> 2, ch = idx & 3;
                uint4 x = *(const uint4*)(g_M1a + (gm0 + row) * (size_t)D_GENE + k0 + ch * 8);
                uint4 y = *(const uint4*)(g_M1b + (gm0 + row) * (size_t)D_GENE + k0 + ch * 8);
                __half2* xh = (__half2*)&x;
                __half2* yh = (__half2*)&y;
                uint4 s;
                __half2* sh = (__half2*)&s;
#pragma unroll
                for (int q = 0; q < 4; q++) sh[q] = __hadd2(xh[q], yh[q]);
                rA[j] = s;
            }
        }
    };
    auto storeA = [&](int buf) {
        if constexpr (DUAL_A) {
            __half* sA = AsP(buf);
#pragma unroll
            for (int j = 0; j < 4; j++) {
                int idx = tid + j * 128;
                int row = idx >> 2, ch = idx & 3;
                *(uint4*)(&sA[row * LDA + ch * 8]) = rA[j];
            }
        }
    };

    // ---- async stage copy: global -> smem, 16B granules (A skipped for MODE 3) ----
    auto load_stage = [&](int it, int buf) {
        const int k0 = kbase + it * 32;
        __half* sB = BsP(buf);
        if constexpr (!DUAL_A) {
            __half* sA = AsP(buf);
#pragma unroll
            for (int j = 0; j < 4; j++) {
                int idx = tid + j * 128;
                int row = idx >> 2, ch = idx & 3;    // A: 128 rows x 4 chunks(16B)
                __pipeline_memcpy_async(&sA[row * LDA + ch * 8],
                                        A + (gm0 + row) * (size_t)K + k0 + ch * 8, 16);
            }
        }
        if (B_COL) {
#pragma unroll
            for (int j = 0; j < 4; j++) {
                int idx = tid + j * 128;
                int row = idx >> 2, ch = idx & 3;
                __pipeline_memcpy_async(&sB[row * 40 + ch * 8],
                                        B + (gn0 + row) * (size_t)K + k0 + ch * 8, 16);
            }
        } else {
#pragma unroll
            for (int j = 0; j < 4; j++) {
                int idx = tid + j * 128;
                int row = idx >> 4, ch = idx & 15;   // 32 rows x 16 chunks
                __pipeline_memcpy_async(&sB[row * 136 + ch * 8],
                                        B + (size_t)(k0 + row) * Ndim + gn0 + ch * 8, 16);
            }
        }
        __pipeline_commit();
    };

    fetchA(0);
    load_stage(0, 0);
    if (NK > 1) load_stage(1, 1);

#pragma unroll 1
    for (int it = 0; it < NK; ++it) {
        const int buf = it % 3;
        storeA(buf);                                   // MODE 3 only: regs -> As[buf]
        if (it == NK - 1) __pipeline_wait_prior(0);    // tail
        else              __pipeline_wait_prior(1);    // stage `it` complete
        __syncthreads();   // tiles visible (BAR drains STS); old reads of reused bufs done
        if (DUAL_A && it + 1 < NK) fetchA(it + 1);
        if (it + 2 < NK) load_stage(it + 2, (it + 2) % 3);

        const __half* sA = AsP(buf);
        const __half* sB = BsP(buf);
#pragma unroll
        for (int kk = 0; kk < 32; kk += 16) {
            if constexpr (B_COL) {
                wmma::fragment<wmma::matrix_b, 16, 16, 16, __half, wmma::col_major> b[4];
#pragma unroll
                for (int nt = 0; nt < 4; nt++)
                    wmma::load_matrix_sync(b[nt], &sB[(wn * 64 + nt * 16) * 40 + kk], 40);
#pragma unroll
                for (int mt = 0; mt < 4; mt++) {
                    wmma::fragment<wmma::matrix_a, 16, 16, 16, __half, wmma::row_major> a;
                    wmma::load_matrix_sync(a, &sA[(wm * 64 + mt * 16) * LDA + kk], LDA);
#pragma unroll
                    for (int nt = 0; nt < 4; nt++)
                        wmma::mma_sync(acc[mt][nt], a, b[nt], acc[mt][nt]);
                }
            } else {
                wmma::fragment<wmma::matrix_b, 16, 16, 16, __half, wmma::row_major> b[4];
#pragma unroll
                for (int nt = 0; nt < 4; nt++)
                    wmma::load_matrix_sync(b[nt], &sB[kk * 136 + wn * 64 + nt * 16], 136);
#pragma unroll
                for (int mt = 0; mt < 4; mt++) {
                    wmma::fragment<wmma::matrix_a, 16, 16, 16, __half, wmma::row_major> a;
                    wmma::load_matrix_sync(a, &sA[(wm * 64 + mt * 16) * LDA + kk], LDA);
#pragma unroll
                    for (int nt = 0; nt < 4; nt++)
                        wmma::mma_sync(acc[mt][nt], a, b[nt], acc[mt][nt]);
                }
            }
        }
    }

    // ---------------- epilogue (per-warp staging; aliases stage 0) ----------------
    __syncthreads();   // all compute done before overwriting stage smem
    float* epbuf = (float*)dsm + w * 320;   // 4 warps x 16x20 floats = 5120 B

    const int r  = lane >> 1;
    const int cb = (lane & 1) * 8;
#pragma unroll
    for (int mt = 0; mt < 4; mt++) {
        const size_t gr = gm0 + wm * 64 + mt * 16 + r;
#pragma unroll
        for (int nt = 0; nt < 4; nt++) {
            wmma::store_matrix_sync(epbuf, acc[mt][nt], 20, wmma::mem_row_major);
            __syncwarp();
            const size_t gc = gn0 + wn * 64 + nt * 16 + cb;
            float v[8];
#pragma unroll
            for (int e = 0; e < 8; e++) v[e] = epbuf[r * 20 + cb + e];

            if constexpr (MODE == 0) {
                __half2 hh[4], ll[4];
#pragma unroll
                for (int e = 0; e < 4; e++) {
                    __half h0 = __float2half_rn(v[e * 2]);
                    __half h1 = __float2half_rn(v[e * 2 + 1]);
                    hh[e] = __halves2half2(h0, h1);
                    ll[e] = __halves2half2(
                        __float2half_rn(v[e * 2]     - __half2float(h0)),
                        __float2half_rn(v[e * 2 + 1] - __half2float(h1)));
                }
                size_t base = gr * KCAT + gc;
                *(uint4*)(g_Acat + base)             = *(uint4*)hh;
                *(uint4*)(g_Acat + base + D_EMB)     = *(uint4*)ll;
                *(uint4*)(g_Acat + base + 2 * D_EMB) = *(uint4*)hh;
            } else if constexpr (MODE == 1) {
                const float* prow = aux + gr * (size_t)N_CELLS + gc;
                float4 p0 = __ldcs((const float4*)prow);
                float4 p1 = __ldcs((const float4*)(prow + 4));
                float pv[8] = {p0.x, p0.y, p0.z, p0.w, p1.x, p1.y, p1.z, p1.w};
                __half2 o[4];
#pragma unroll
                for (int e = 0; e < 4; e++) {
                    float s0 = gate_fn(pv[e * 2],     v[e * 2]);
                    float s1 = gate_fn(pv[e * 2 + 1], v[e * 2 + 1]);
                    o[e] = __floats2half2_rn(s0, s1);
                }
                *(uint4*)(g_gated + gr * (size_t)N_CELLS + gc) = *(uint4*)o;
            } else if constexpr (MODE == 2) {
                __half* dst = blockIdx.z ? g_M1b : g_M1a;
                __half2 o[4];
#pragma unroll
                for (int e = 0; e < 4; e++)
                    o[e] = __floats2half2_rn(v[e * 2], v[e * 2 + 1]);
                *(uint4*)(dst + gr * D_GENE + gc) = *(uint4*)o;
            } else {
                float4 o0 = make_float4(v[0] * (1.0f / 1024.0f), v[1] * (1.0f / 1024.0f),
                                        v[2] * (1.0f / 1024.0f), v[3] * (1.0f / 1024.0f));
                float4 o1 = make_float4(v[4] * (1.0f / 1024.0f), v[5] * (1.0f / 1024.0f),
                                        v[6] * (1.0f / 1024.0f), v[7] * (1.0f / 1024.0f));
                *(float4*)(outf + gr * D_GENE + gc)     = o0;
                *(float4*)(outf + gr * D_GENE + gc + 4) = o1;
            }
            __syncwarp();
        }
    }
}

// ---------------- launch ----------------
extern "C" void kernel_launch(void* const* d_in, const int* in_sizes, int n_in,
                              void* d_out, int out_size) {
    const float* expr = (const float*)d_in[0];
    const float* enc  = (const float*)d_in[1];
    const float* pd   = (const float*)d_in[2];
    const float* T    = (const float*)d_in[3];
    const float* gr   = (const float*)d_in[4];
    float* out = (float*)d_out;

    cudaFuncSetAttribute(gemm_wmma12<0>, cudaFuncAttributeMaxDynamicSharedMemorySize, DSMEM_B);
    cudaFuncSetAttribute(gemm_wmma12<1>, cudaFuncAttributeMaxDynamicSharedMemorySize, DSMEM_B);
    cudaFuncSetAttribute(gemm_wmma12<2>, cudaFuncAttributeMaxDynamicSharedMemorySize, DSMEM_B);
    cudaFuncSetAttribute(gemm_wmma12<3>, cudaFuncAttributeMaxDynamicSharedMemorySize, DSMEM_B);

    // Order chosen so the 4th launch (ncu capture slot) is the dominant GEMM1.
    k_cvt_enc<<<(N_CELLS * D_EMB) / 256, 256>>>(enc);
    k_cvt_T<<<(D_EMB * D_EMB) / 256, 256>>>(T);
    gemm_wmma12<0><<<dim3(D_EMB / 128,  N_CELLS / 128), 128, DSMEM_B>>>(nullptr, nullptr);
    gemm_wmma12<1><<<dim3(N_CELLS / 128, N_CELLS / 128), 128, DSMEM_B>>>(pd, nullptr);
    k_cvt_expr<<<(N_CELLS * D_GENE) / 256, 256>>>(expr);
    k_cvt_gr<<<(D_GENE * D_GENE) / 256, 256>>>(gr);
    // GEMM2: split-K=2 in ONE launch (grid.z) -> 1024 CTAs, kills wave quantization
    gemm_wmma12<2><<<dim3(D_GENE / 128, N_CELLS / 128, 2), 128, DSMEM_B>>>(nullptr, nullptr);
    // GEMM3: A = M1a + M1b summed in the A-load path
    gemm_wmma12<3><<<dim3(D_GENE / 128, N_CELLS / 128), 128, DSMEM_B>>>(nullptr, out);
}